// round 14
// baseline (speedup 1.0000x reference)
#include <cuda_runtime.h>
#include <cuda_fp16.h>
#include <cstdint>

// ---------------------------------------------------------------------------
// MixtureDecoder: soft-tree gating -> leaf mixture -> 3x ConvTranspose2d(4,2,1)
// All convs: implicit-GEMM fp16 mma.sync m16n8k16 (fp32 accum).
// NHWC fp16 inter-layer activations; staging = cp.async 16B; epilogue =
// coalesced half2. A via ldmatrix.x4 (k-order [icg8][tap][icl8]).
// KCH=256 weight chunks, double-buffered, ONE __syncthreads per chunk.
// R14 fix: conv1 warp tiling MG=2/MT=4 (8 m-tiles = 128 quads), NG=8/NT=2.
// ---------------------------------------------------------------------------

#define B_ 512

__device__ float  g_lp[B_ * 32];                     // leaf probs
__device__ __half g_x0[(size_t)B_ * 64 * 128];       // mix out NHWC [b][s][c]
__device__ __half g_a1[(size_t)B_ * 256 * 128];      // conv1 out NHWC
__device__ __half g_a2[(size_t)B_ * 1024 * 64];      // conv2 out NHWC
__device__ uint32_t g_w1t[4 * 256 * 128];            // conv1 W [p][k/2][oc] h2
__device__ uint32_t g_w2t[4 * 256 * 64];             // conv2 W
__device__ uint32_t g_w3t[4 * 128 * 8];              // conv3 W (oc pad to 8)

// ---------------- helpers ---------------------------------------------------
__device__ __forceinline__ void mma_f16(float* c, const uint32_t* a,
                                        uint32_t b0v, uint32_t b1v) {
    asm volatile(
        "mma.sync.aligned.m16n8k16.row.col.f32.f16.f16.f32 "
        "{%0,%1,%2,%3}, {%4,%5,%6,%7}, {%8,%9}, {%0,%1,%2,%3};\n"
        : "+f"(c[0]), "+f"(c[1]), "+f"(c[2]), "+f"(c[3])
        : "r"(a[0]), "r"(a[1]), "r"(a[2]), "r"(a[3]), "r"(b0v), "r"(b1v));
}

__device__ __forceinline__ void ldsm_x4(uint32_t* r, uint32_t addr) {
    asm volatile(
        "ldmatrix.sync.aligned.m8n8.x4.shared.b16 {%0,%1,%2,%3}, [%4];"
        : "=r"(r[0]), "=r"(r[1]), "=r"(r[2]), "=r"(r[3]) : "r"(addr));
}

__device__ __forceinline__ void cp_async16(uint32_t dst, const void* src) {
    asm volatile("cp.async.cg.shared.global [%0], [%1], 16;"
                 :: "r"(dst), "l"(src));
}

__device__ __forceinline__ void stv(__half* p, float v) { *p = __float2half(v); }
__device__ __forceinline__ void stv(float* p, float v) { *p = v; }

// ---------------- weight pre-pack: k-order [icg8][tap][icl8] ---------------
template <int IC, int OCP, int OCV>
__device__ __forceinline__ void wprep_body(int idx, const float* __restrict__ W,
                                           uint32_t* __restrict__ Wt) {
    constexpr int K2 = 2 * IC;
    int n = idx % OCP;
    int pr = (idx / OCP) % K2;
    int p = idx / (OCP * K2);
    int py = p >> 1, px = p & 1;
    __half h[2];
    #pragma unroll
    for (int j = 0; j < 2; ++j) {
        int k = 2 * pr + j;
        int icl8 = k & 7;
        int tap = (k >> 3) & 3;
        int ic = (k >> 5) * 8 + icl8;
        int ddy = tap >> 1, ddx = tap & 1;
        int ky = 3 - py - 2 * ddy, kx = 3 - px - 2 * ddx;
        float v = (n < OCV) ? W[((size_t)ic * OCV + n) * 16 + ky * 4 + kx] : 0.0f;
        h[j] = __float2half(v);
    }
    Wt[idx] = (uint32_t)*reinterpret_cast<unsigned short*>(&h[0])
            | ((uint32_t)*reinterpret_cast<unsigned short*>(&h[1]) << 16);
}

// ---------------- fused prep: 3x weight pack + gating/leaf probs -----------
__global__ __launch_bounds__(256) void prep_kernel(
    const float* __restrict__ x, const float* __restrict__ gw,
    const float* __restrict__ gb, const float* __restrict__ w1,
    const float* __restrict__ w2, const float* __restrict__ w3) {
    int bid = blockIdx.x;
    int t = threadIdx.x;

    if (bid < 512) {
        wprep_body<128, 128, 128>(bid * 256 + t, w1, g_w1t);
    } else if (bid < 768) {
        wprep_body<128, 64, 64>((bid - 512) * 256 + t, w2, g_w2t);
    } else if (bid < 784) {
        wprep_body<64, 8, 3>((bid - 768) * 256 + t, w3, g_w3t);
    } else {
        int w = t >> 5, lane = t & 31;
        int b = (bid - 784) * 8 + w;
        float g = 0.0f;
        if (lane < 31) {
            float p = gb[lane];
            const float* xb = x + b * 128;
            #pragma unroll 8
            for (int i = 0; i < 128; ++i)
                p += xb[i] * gw[i * 31 + lane];
            g = 1.0f / (1.0f + expf(-p));
        }
        float lp = 1.0f;
        int prefix = 0;
        #pragma unroll
        for (int d = 1; d <= 5; ++d) {
            int node = (1 << (d - 1)) - 1 + prefix;
            float gate = __shfl_sync(0xffffffffu, g, node);
            int bit = (lane >> (5 - d)) & 1;
            lp *= bit ? (1.0f - gate) : gate;
            prefix = (prefix << 1) | bit;
        }
        g_lp[b * 32 + lane] = lp;
    }
}

// ---------------- mixture -> NHWC fp16: x0[b][s][c] ------------------------
__global__ __launch_bounds__(256) void mix_kernel(const float* __restrict__ z) {
    int cp = threadIdx.x & 63;               // channel pair 0..63
    int c = cp * 2;
    int s = blockIdx.x * 4 + (threadIdx.x >> 6);   // spatial 0..63
    int r0 = c * 64 + s, r1 = r0 + 64;       // z rows (f = ch*64 + s)

    float zr0[32], zr1[32];
    #pragma unroll
    for (int l4 = 0; l4 < 8; ++l4) {
        float4 v = *reinterpret_cast<const float4*>(z + (size_t)r0 * 32 + l4 * 4);
        zr0[l4 * 4 + 0] = v.x; zr0[l4 * 4 + 1] = v.y;
        zr0[l4 * 4 + 2] = v.z; zr0[l4 * 4 + 3] = v.w;
        float4 u = *reinterpret_cast<const float4*>(z + (size_t)(r1) * 32 + l4 * 4);
        zr1[l4 * 4 + 0] = u.x; zr1[l4 * 4 + 1] = u.y;
        zr1[l4 * 4 + 2] = u.z; zr1[l4 * 4 + 3] = u.w;
    }

    __shared__ float s_lp[32][32];
    for (int bt = 0; bt < 16; ++bt) {
        int b0 = bt * 32;
        __syncthreads();
        for (int i = threadIdx.x; i < 1024; i += 256)
            s_lp[i >> 5][i & 31] = g_lp[b0 * 32 + i];
        __syncthreads();
        #pragma unroll 4
        for (int bi = 0; bi < 32; ++bi) {
            float a0 = 0.0f, a1 = 0.0f;
            #pragma unroll
            for (int l = 0; l < 32; ++l) {
                float sv = s_lp[bi][l];
                a0 += zr0[l] * sv;
                a1 += zr1[l] * sv;
            }
            *reinterpret_cast<__half2*>(
                g_x0 + ((size_t)(b0 + bi) * 64 + s) * 128 + c) =
                __floats2half2_rn(a0, a1);
        }
    }
}

// ---------------- ConvT(4,2,1) implicit GEMM, fp16 m16n8k16 ----------------
// NHWC input [b][iy*JW+ix][IC]; smem s_in[bl][(ry*SR+cx)][ic], SIT=IC+8.
// A via ldmatrix.x4; B staged in KCH-row chunks, 2 buffers, 1 sync/chunk:
//   wait_group 0 -> __syncthreads -> issue chunk t+1 -> compute chunk t.
template <int JH, int JHT, int JW, int IC, int OC, int OCV, int NB,
          int MGROUPS, int NGROUPS, int MT_W, int NT_W, int NWARPS,
          int WBS2, bool RELU, typename TO, int MINB, bool ONHWC, int KCH>
__global__ __launch_bounds__(NWARPS * 32, MINB) void convt_mma_kernel(
    const __half* __restrict__ in, const uint32_t* __restrict__ Wt,
    const float* __restrict__ bias, TO* __restrict__ out) {
    constexpr int SR = JW + 2;
    constexpr int CH = (JHT + 2) * SR;
    constexpr int SIT = IC + 8;              // smem stride (halfs), 16B mult
    constexpr int ZROW = SIT / 8;            // uint4 per position
    constexpr int PP = IC / 8;               // 16B pieces per position
    constexpr int KTOT = 4 * IC;
    constexpr int NKCH = KTOT / KCH;         // chunks per parity
    constexpr int NCH = 4 * NKCH;            // total chunks
    constexpr int SPC = KCH / 16;            // s-steps per chunk
    constexpr int Q = JHT * JW;
    constexpr int IN_ALLOC = NB * CH * SIT;  // halfs
    constexpr int NT = NWARPS * 32;
    constexpr int OH = 2 * JH, OW = 2 * JW;
    constexpr int PIECES = (KCH / 2) * (OC / 4);
    constexpr int CHUNK_U32 = (KCH / 2) * WBS2;

    extern __shared__ char smem_raw[];
    __half* s_in = reinterpret_cast<__half*>(smem_raw);
    uint32_t* s_wb[2] = {
        reinterpret_cast<uint32_t*>(smem_raw + IN_ALLOC * 2),
        reinterpret_cast<uint32_t*>(smem_raw + IN_ALLOC * 2) + CHUNK_U32};
    uint32_t wb_u32[2] = {(uint32_t)__cvta_generic_to_shared(s_wb[0]),
                          (uint32_t)__cvta_generic_to_shared(s_wb[1])};
    const uint32_t s_in_b = (uint32_t)__cvta_generic_to_shared(s_in);

    const int tid = threadIdx.x;
    const int lane = tid & 31;
    const int w = tid >> 5;
    const int mg = w % MGROUPS;
    const int ng = w / MGROUPS;
    const int q = lane & 3;                  // B row / epilogue lane quad
    const int ln4 = lane >> 2;
    const int mrow = (lane & 7) + ((lane >> 3) & 1) * 8;
    const int lddx = (lane >> 4) & 1;

    const int b0 = blockIdx.x * NB;
    const int jy0 = blockIdx.y * JHT;

    // ---- halo zero-fill (side cols + invalid rows), STS.128 ----
    {
        uint4 zz = make_uint4(0, 0, 0, 0);
        uint4* s_in4 = reinterpret_cast<uint4*>(s_in);
        for (int i = tid; i < NB * (JHT + 2) * 2 * ZROW; i += NT) {
            int sub = i % ZROW;
            int pos = i / ZROW;
            int side = pos & 1;
            int ry = (pos >> 1) % (JHT + 2);
            int bl = (pos >> 1) / (JHT + 2);
            int rr = ry * SR + (side ? SR - 1 : 0);
            s_in4[(bl * CH + rr) * ZROW + sub] = zz;
        }
        #pragma unroll
        for (int e = 0; e < 2; ++e) {
            int ry = e ? JHT + 1 : 0;
            int iy = jy0 + ry - 1;
            if (iy < 0 || iy >= JH) {
                for (int i = tid; i < NB * JW * ZROW; i += NT) {
                    int sub = i % ZROW;
                    int pos = i / ZROW;
                    int jx = pos % JW;
                    int bl = pos / JW;
                    s_in4[(bl * CH + ry * SR + 1 + jx) * ZROW + sub] = zz;
                }
            }
        }
    }
    // ---- interior rows: cp.async 16B pieces from NHWC gmem ----
    {
        for (int i = tid; i < NB * (JHT + 2) * JW * PP; i += NT) {
            int sub = i % PP;
            int t1 = i / PP;
            int jx = t1 % JW;
            int t2 = t1 / JW;
            int ry = t2 % (JHT + 2);
            int bl = t2 / (JHT + 2);
            int iy = jy0 + ry - 1;
            if (iy >= 0 && iy < JH) {
                uint32_t dst = s_in_b
                    + ((bl * CH + ry * SR + 1 + jx) * SIT + sub * 8) * 2;
                const __half* src = in
                    + (((size_t)(b0 + bl) * JH + iy) * JW + jx) * IC + sub * 8;
                cp_async16(dst, src);
            }
        }
        asm volatile("cp.async.commit_group;");
    }

    // weight-chunk issue (chunk index u over all parities)
    auto issue_chunk = [&](int u) {
        int pu = u / NKCH, ku = u % NKCH;
        const uint32_t* src =
            Wt + ((size_t)pu * (KTOT / 2) + ku * (KCH / 2)) * OC;
        uint32_t db = wb_u32[u & 1];
        for (int i = tid; i < PIECES; i += NT) {
            int row = i / (OC / 4), col = i % (OC / 4);
            cp_async16(db + (row * WBS2 + col * 4) * 4, src + row * OC + col * 4);
        }
        asm volatile("cp.async.commit_group;");
    };
    issue_chunk(0);

    for (int p = 0; p < 4; ++p) {
        const int py = p >> 1, px = p & 1;

        // per-lane ldmatrix base addresses (ddy=0), bytes
        uint32_t abase[MT_W];
        #pragma unroll
        for (int mi = 0; mi < MT_W; ++mi) {
            int m0 = (mg + mi * MGROUPS) * 16;
            int qq = m0 + mrow;
            int bl = qq / Q;
            int q2 = qq % Q;
            int jy = q2 / JW, jx = q2 % JW;
            abase[mi] = s_in_b
                + (uint32_t)((bl * CH + (jy + py) * SR + jx + lddx + px) * SIT)
                  * 2;
        }

        float acc[MT_W][NT_W][4];
        #pragma unroll
        for (int mi = 0; mi < MT_W; ++mi)
            #pragma unroll
            for (int ni = 0; ni < NT_W; ++ni)
                #pragma unroll
                for (int k = 0; k < 4; ++k) acc[mi][ni][k] = 0.0f;

        for (int kc = 0; kc < NKCH; ++kc) {
            const int t = p * NKCH + kc;
            asm volatile("cp.async.wait_group 0;");
            __syncthreads();           // chunk t visible; chunk t-1 reads done
            if (t + 1 < NCH) issue_chunk(t + 1);

            const uint32_t* wb = s_wb[t & 1];
            #pragma unroll
            for (int s = 0; s < SPC; ++s) {
                const int ss = kc * SPC + s;     // global s-step in parity
                const uint32_t aoff = (uint32_t)((ss & 1) * SR * SIT * 2
                                                 + (ss >> 1) * 16);
                uint32_t a[MT_W][4];
                #pragma unroll
                for (int mi = 0; mi < MT_W; ++mi)
                    ldsm_x4(a[mi], abase[mi] + aoff);
                const uint32_t* sb = wb + (s * 8 + q) * WBS2 + ln4;
                #pragma unroll
                for (int ni = 0; ni < NT_W; ++ni) {
                    int n0 = (ng * NT_W + ni) * 8;
                    uint32_t bb0 = sb[n0];
                    uint32_t bb1 = sb[n0 + 4 * WBS2];
                    #pragma unroll
                    for (int mi = 0; mi < MT_W; ++mi)
                        mma_f16(acc[mi][ni], a[mi], bb0, bb1);
                }
            }
        }

        // ---- epilogue (overlaps next parity's weight cp.async) ----
        #pragma unroll
        for (int mi = 0; mi < MT_W; ++mi) {
            int m0 = (mg + mi * MGROUPS) * 16;
            int bl = m0 / Q;
            int q0 = m0 % Q;
            #pragma unroll
            for (int ni = 0; ni < NT_W; ++ni) {
                int oc = (ng * NT_W + ni) * 8 + 2 * q;
                if (ONHWC) {
                    float bv0 = bias[oc], bv1 = bias[oc + 1];
                    #pragma unroll
                    for (int h = 0; h < 2; ++h) {
                        int qq = q0 + ln4 + h * 8;
                        int jy = qq / JW, jx = qq % JW;
                        int oy = 2 * (jy0 + jy) + py, ox = 2 * jx + px;
                        float v0 = acc[mi][ni][2 * h + 0] + bv0;
                        float v1 = acc[mi][ni][2 * h + 1] + bv1;
                        if (RELU) { v0 = fmaxf(v0, 0.0f); v1 = fmaxf(v1, 0.0f); }
                        size_t o = ((size_t)(b0 + bl) * OH * OW
                                    + (size_t)oy * OW + ox) * OC + oc;
                        *reinterpret_cast<__half2*>(
                            reinterpret_cast<__half*>(out) + o) =
                            __floats2half2_rn(v0, v1);
                    }
                } else {
                    bool v0ok = (OCV == OC) || (oc < OCV);
                    bool v1ok = (OCV == OC) || (oc + 1 < OCV);
                    float bv0 = v0ok ? bias[oc] : 0.0f;
                    float bv1 = v1ok ? bias[oc + 1] : 0.0f;
                    #pragma unroll
                    for (int h = 0; h < 2; ++h) {
                        int qq = q0 + ln4 + h * 8;
                        int jy = qq / JW, jx = qq % JW;
                        int oy = 2 * (jy0 + jy) + py, ox = 2 * jx + px;
                        size_t o = (((size_t)(b0 + bl) * OCV + oc) * OH + oy)
                                   * OW + ox;
                        float v0 = acc[mi][ni][2 * h + 0] + bv0;
                        float v1 = acc[mi][ni][2 * h + 1] + bv1;
                        if (RELU) { v0 = fmaxf(v0, 0.0f); v1 = fmaxf(v1, 0.0f); }
                        if (v0ok) stv(out + o, v0);
                        if (v1ok) stv(out + o + (size_t)OH * OW, v1);
                    }
                }
            }
        }
    }
}

// ---------------------------------------------------------------------------
extern "C" void kernel_launch(void* const* d_in, const int* in_sizes, int n_in,
                              void* d_out, int out_size) {
    (void)in_sizes; (void)n_in; (void)out_size;
    const float* x  = (const float*)d_in[0];
    const float* gw = (const float*)d_in[1];
    const float* gb = (const float*)d_in[2];
    const float* z  = (const float*)d_in[3];
    const float* w1 = (const float*)d_in[4];
    const float* b1 = (const float*)d_in[5];
    const float* w2 = (const float*)d_in[6];
    const float* b2 = (const float*)d_in[7];
    const float* w3 = (const float*)d_in[8];
    const float* b3 = (const float*)d_in[9];
    float* out = (float*)d_out;

    __half *px0, *pa1, *pa2;
    uint32_t *pw1t, *pw2t, *pw3t;
    cudaGetSymbolAddress((void**)&px0, g_x0);
    cudaGetSymbolAddress((void**)&pa1, g_a1);
    cudaGetSymbolAddress((void**)&pa2, g_a2);
    cudaGetSymbolAddress((void**)&pw1t, g_w1t);
    cudaGetSymbolAddress((void**)&pw2t, g_w2t);
    cudaGetSymbolAddress((void**)&pw3t, g_w3t);

    // conv1: NB=2 (M=128 -> 8 m-tiles): MG=2/MT=4; OC=128 -> NG=8/NT=2; KCH=256
    constexpr int S1 = 2 * 100 * 136 * 2 + 2 * 128 * 136 * 4;  // 193,664
    // conv2: NB=1 (M=256 -> 16 m-tiles): MG=4/MT=4; OC=64 -> NG=4/NT=2; KCH=256
    constexpr int S2 = 324 * 136 * 2 + 2 * 128 * 72 * 4;       // 161,856
    // conv3: JHT=16 (M=512 -> 32 m-tiles): MG=8/MT=4; NG=1/NT=1; KCH=256
    constexpr int S3 = 612 * 72 * 2 + 2 * 128 * 8 * 4;         // 96,320

    auto k1 = convt_mma_kernel<8, 8, 8, 128, 128, 128, 2, 2, 8, 4, 2, 16, 136,
                               true, __half, 1, true, 256>;
    auto k2 = convt_mma_kernel<16, 16, 16, 128, 64, 64, 1, 4, 4, 4, 2, 16, 72,
                               true, __half, 1, true, 256>;
    auto k3 = convt_mma_kernel<32, 16, 32, 64, 8, 3, 1, 8, 1, 4, 1, 8, 8,
                               false, float, 2, false, 256>;

    cudaFuncSetAttribute(k1, cudaFuncAttributeMaxDynamicSharedMemorySize, S1);
    cudaFuncSetAttribute(k2, cudaFuncAttributeMaxDynamicSharedMemorySize, S2);
    cudaFuncSetAttribute(k3, cudaFuncAttributeMaxDynamicSharedMemorySize, S3);

    prep_kernel<<<848, 256>>>(x, gw, gb, w1, w2, w3);
    mix_kernel<<<16, 256>>>(z);

    k1<<<dim3(B_ / 2, 1), 512, S1>>>(px0, pw1t, b1, pa1);
    k2<<<dim3(B_, 1), 512, S2>>>(pa1, pw2t, b2, pa2);
    k3<<<dim3(B_, 2), 256, S3>>>(pa2, pw3t, b3, out);
}

// round 16
// speedup vs baseline: 1.6148x; 1.6148x over previous
#include <cuda_runtime.h>
#include <cuda_fp16.h>
#include <cstdint>

// ---------------------------------------------------------------------------
// MixtureDecoder: soft-tree gating -> leaf mixture -> 3x ConvTranspose2d(4,2,1)
// All convs: implicit-GEMM fp16 mma.sync m16n8k16 (fp32 accum).
// NHWC fp16 inter-layer activations; staging = cp.async 16B; epilogue =
// coalesced half2. A via ldmatrix.x4 (k-order [icg8][tap][icl8]).
// R15: R12 CTA shapes (256 thr, 2 CTAs/SM) + single-__syncthreads-per-chunk
// double-buffered weight pipeline (KCH=64).
// ---------------------------------------------------------------------------

#define B_ 512

__device__ float  g_lp[B_ * 32];                     // leaf probs
__device__ __half g_x0[(size_t)B_ * 64 * 128];       // mix out NHWC [b][s][c]
__device__ __half g_a1[(size_t)B_ * 256 * 128];      // conv1 out NHWC
__device__ __half g_a2[(size_t)B_ * 1024 * 64];      // conv2 out NHWC
__device__ uint32_t g_w1t[4 * 256 * 128];            // conv1 W [p][k/2][oc] h2
__device__ uint32_t g_w2t[4 * 256 * 64];             // conv2 W
__device__ uint32_t g_w3t[4 * 128 * 8];              // conv3 W (oc pad to 8)

// ---------------- helpers ---------------------------------------------------
__device__ __forceinline__ void mma_f16(float* c, const uint32_t* a,
                                        uint32_t b0v, uint32_t b1v) {
    asm volatile(
        "mma.sync.aligned.m16n8k16.row.col.f32.f16.f16.f32 "
        "{%0,%1,%2,%3}, {%4,%5,%6,%7}, {%8,%9}, {%0,%1,%2,%3};\n"
        : "+f"(c[0]), "+f"(c[1]), "+f"(c[2]), "+f"(c[3])
        : "r"(a[0]), "r"(a[1]), "r"(a[2]), "r"(a[3]), "r"(b0v), "r"(b1v));
}

__device__ __forceinline__ void ldsm_x4(uint32_t* r, uint32_t addr) {
    asm volatile(
        "ldmatrix.sync.aligned.m8n8.x4.shared.b16 {%0,%1,%2,%3}, [%4];"
        : "=r"(r[0]), "=r"(r[1]), "=r"(r[2]), "=r"(r[3]) : "r"(addr));
}

__device__ __forceinline__ void cp_async16(uint32_t dst, const void* src) {
    asm volatile("cp.async.cg.shared.global [%0], [%1], 16;"
                 :: "r"(dst), "l"(src));
}

__device__ __forceinline__ void stv(__half* p, float v) { *p = __float2half(v); }
__device__ __forceinline__ void stv(float* p, float v) { *p = v; }

// ---------------- weight pre-pack: k-order [icg8][tap][icl8] ---------------
template <int IC, int OCP, int OCV>
__device__ __forceinline__ void wprep_body(int idx, const float* __restrict__ W,
                                           uint32_t* __restrict__ Wt) {
    constexpr int K2 = 2 * IC;
    int n = idx % OCP;
    int pr = (idx / OCP) % K2;
    int p = idx / (OCP * K2);
    int py = p >> 1, px = p & 1;
    __half h[2];
    #pragma unroll
    for (int j = 0; j < 2; ++j) {
        int k = 2 * pr + j;
        int icl8 = k & 7;
        int tap = (k >> 3) & 3;
        int ic = (k >> 5) * 8 + icl8;
        int ddy = tap >> 1, ddx = tap & 1;
        int ky = 3 - py - 2 * ddy, kx = 3 - px - 2 * ddx;
        float v = (n < OCV) ? W[((size_t)ic * OCV + n) * 16 + ky * 4 + kx] : 0.0f;
        h[j] = __float2half(v);
    }
    Wt[idx] = (uint32_t)*reinterpret_cast<unsigned short*>(&h[0])
            | ((uint32_t)*reinterpret_cast<unsigned short*>(&h[1]) << 16);
}

// ---------------- fused prep: 3x weight pack + gating/leaf probs -----------
__global__ __launch_bounds__(256) void prep_kernel(
    const float* __restrict__ x, const float* __restrict__ gw,
    const float* __restrict__ gb, const float* __restrict__ w1,
    const float* __restrict__ w2, const float* __restrict__ w3) {
    int bid = blockIdx.x;
    int t = threadIdx.x;

    if (bid < 512) {
        wprep_body<128, 128, 128>(bid * 256 + t, w1, g_w1t);
    } else if (bid < 768) {
        wprep_body<128, 64, 64>((bid - 512) * 256 + t, w2, g_w2t);
    } else if (bid < 784) {
        wprep_body<64, 8, 3>((bid - 768) * 256 + t, w3, g_w3t);
    } else {
        int w = t >> 5, lane = t & 31;
        int b = (bid - 784) * 8 + w;
        float g = 0.0f;
        if (lane < 31) {
            float p = gb[lane];
            const float* xb = x + b * 128;
            #pragma unroll 8
            for (int i = 0; i < 128; ++i)
                p += xb[i] * gw[i * 31 + lane];
            g = 1.0f / (1.0f + expf(-p));
        }
        float lp = 1.0f;
        int prefix = 0;
        #pragma unroll
        for (int d = 1; d <= 5; ++d) {
            int node = (1 << (d - 1)) - 1 + prefix;
            float gate = __shfl_sync(0xffffffffu, g, node);
            int bit = (lane >> (5 - d)) & 1;
            lp *= bit ? (1.0f - gate) : gate;
            prefix = (prefix << 1) | bit;
        }
        g_lp[b * 32 + lane] = lp;
    }
}

// ---------------- mixture -> NHWC fp16: x0[b][s][c] ------------------------
__global__ __launch_bounds__(256) void mix_kernel(const float* __restrict__ z) {
    int cp = threadIdx.x & 63;               // channel pair 0..63
    int c = cp * 2;
    int s = blockIdx.x * 4 + (threadIdx.x >> 6);   // spatial 0..63
    int r0 = c * 64 + s, r1 = r0 + 64;       // z rows (f = ch*64 + s)

    float zr0[32], zr1[32];
    #pragma unroll
    for (int l4 = 0; l4 < 8; ++l4) {
        float4 v = *reinterpret_cast<const float4*>(z + (size_t)r0 * 32 + l4 * 4);
        zr0[l4 * 4 + 0] = v.x; zr0[l4 * 4 + 1] = v.y;
        zr0[l4 * 4 + 2] = v.z; zr0[l4 * 4 + 3] = v.w;
        float4 u = *reinterpret_cast<const float4*>(z + (size_t)r1 * 32 + l4 * 4);
        zr1[l4 * 4 + 0] = u.x; zr1[l4 * 4 + 1] = u.y;
        zr1[l4 * 4 + 2] = u.z; zr1[l4 * 4 + 3] = u.w;
    }

    __shared__ float s_lp[32][32];
    for (int bt = 0; bt < 16; ++bt) {
        int b0 = bt * 32;
        __syncthreads();
        for (int i = threadIdx.x; i < 1024; i += 256)
            s_lp[i >> 5][i & 31] = g_lp[b0 * 32 + i];
        __syncthreads();
        #pragma unroll 4
        for (int bi = 0; bi < 32; ++bi) {
            float a0 = 0.0f, a1 = 0.0f;
            #pragma unroll
            for (int l = 0; l < 32; ++l) {
                float sv = s_lp[bi][l];
                a0 += zr0[l] * sv;
                a1 += zr1[l] * sv;
            }
            *reinterpret_cast<__half2*>(
                g_x0 + ((size_t)(b0 + bi) * 64 + s) * 128 + c) =
                __floats2half2_rn(a0, a1);
        }
    }
}

// ---------------- ConvT(4,2,1) implicit GEMM, fp16 m16n8k16 ----------------
// NHWC input [b][iy*JW+ix][IC]; smem s_in[bl][(ry*SR+cx)][ic], SIT=IC+8.
// A via ldmatrix.x4; B staged in KCH-row chunks, 2 buffers, 1 sync/chunk:
//   wait_group 0 -> __syncthreads -> issue chunk t+1 -> compute chunk t.
template <int JH, int JHT, int JW, int IC, int OC, int OCV, int NB,
          int MGROUPS, int NGROUPS, int MT_W, int NT_W, int NWARPS,
          int WBS2, bool RELU, typename TO, int MINB, bool ONHWC, int KCH>
__global__ __launch_bounds__(NWARPS * 32, MINB) void convt_mma_kernel(
    const __half* __restrict__ in, const uint32_t* __restrict__ Wt,
    const float* __restrict__ bias, TO* __restrict__ out) {
    constexpr int SR = JW + 2;
    constexpr int CH = (JHT + 2) * SR;
    constexpr int SIT = IC + 8;              // smem stride (halfs), 16B mult
    constexpr int ZROW = SIT / 8;            // uint4 per position
    constexpr int PP = IC / 8;               // 16B pieces per position
    constexpr int KTOT = 4 * IC;
    constexpr int NKCH = KTOT / KCH;         // chunks per parity
    constexpr int NCH = 4 * NKCH;            // total chunks
    constexpr int SPC = KCH / 16;            // s-steps per chunk
    constexpr int Q = JHT * JW;
    constexpr int IN_ALLOC = NB * CH * SIT;  // halfs
    constexpr int NT = NWARPS * 32;
    constexpr int OH = 2 * JH, OW = 2 * JW;
    constexpr int PIECES = (KCH / 2) * (OC / 4);
    constexpr int CHUNK_U32 = (KCH / 2) * WBS2;

    extern __shared__ char smem_raw[];
    __half* s_in = reinterpret_cast<__half*>(smem_raw);
    uint32_t* s_wb[2] = {
        reinterpret_cast<uint32_t*>(smem_raw + IN_ALLOC * 2),
        reinterpret_cast<uint32_t*>(smem_raw + IN_ALLOC * 2) + CHUNK_U32};
    uint32_t wb_u32[2] = {(uint32_t)__cvta_generic_to_shared(s_wb[0]),
                          (uint32_t)__cvta_generic_to_shared(s_wb[1])};
    const uint32_t s_in_b = (uint32_t)__cvta_generic_to_shared(s_in);

    const int tid = threadIdx.x;
    const int lane = tid & 31;
    const int w = tid >> 5;
    const int mg = w % MGROUPS;
    const int ng = w / MGROUPS;
    const int q = lane & 3;                  // B row / epilogue lane quad
    const int ln4 = lane >> 2;
    const int mrow = (lane & 7) + ((lane >> 3) & 1) * 8;
    const int lddx = (lane >> 4) & 1;

    const int b0 = blockIdx.x * NB;
    const int jy0 = blockIdx.y * JHT;

    // ---- halo zero-fill (side cols + invalid rows), STS.128 ----
    {
        uint4 zz = make_uint4(0, 0, 0, 0);
        uint4* s_in4 = reinterpret_cast<uint4*>(s_in);
        for (int i = tid; i < NB * (JHT + 2) * 2 * ZROW; i += NT) {
            int sub = i % ZROW;
            int pos = i / ZROW;
            int side = pos & 1;
            int ry = (pos >> 1) % (JHT + 2);
            int bl = (pos >> 1) / (JHT + 2);
            int rr = ry * SR + (side ? SR - 1 : 0);
            s_in4[(bl * CH + rr) * ZROW + sub] = zz;
        }
        #pragma unroll
        for (int e = 0; e < 2; ++e) {
            int ry = e ? JHT + 1 : 0;
            int iy = jy0 + ry - 1;
            if (iy < 0 || iy >= JH) {
                for (int i = tid; i < NB * JW * ZROW; i += NT) {
                    int sub = i % ZROW;
                    int pos = i / ZROW;
                    int jx = pos % JW;
                    int bl = pos / JW;
                    s_in4[(bl * CH + ry * SR + 1 + jx) * ZROW + sub] = zz;
                }
            }
        }
    }
    // ---- interior rows: cp.async 16B pieces from NHWC gmem ----
    {
        for (int i = tid; i < NB * (JHT + 2) * JW * PP; i += NT) {
            int sub = i % PP;
            int t1 = i / PP;
            int jx = t1 % JW;
            int t2 = t1 / JW;
            int ry = t2 % (JHT + 2);
            int bl = t2 / (JHT + 2);
            int iy = jy0 + ry - 1;
            if (iy >= 0 && iy < JH) {
                uint32_t dst = s_in_b
                    + ((bl * CH + ry * SR + 1 + jx) * SIT + sub * 8) * 2;
                const __half* src = in
                    + (((size_t)(b0 + bl) * JH + iy) * JW + jx) * IC + sub * 8;
                cp_async16(dst, src);
            }
        }
        asm volatile("cp.async.commit_group;");
    }

    // weight-chunk issue (chunk index u over all parities)
    auto issue_chunk = [&](int u) {
        int pu = u / NKCH, ku = u % NKCH;
        const uint32_t* src =
            Wt + ((size_t)pu * (KTOT / 2) + ku * (KCH / 2)) * OC;
        uint32_t db = wb_u32[u & 1];
        for (int i = tid; i < PIECES; i += NT) {
            int row = i / (OC / 4), col = i % (OC / 4);
            cp_async16(db + (row * WBS2 + col * 4) * 4, src + row * OC + col * 4);
        }
        asm volatile("cp.async.commit_group;");
    };
    issue_chunk(0);

    for (int p = 0; p < 4; ++p) {
        const int py = p >> 1, px = p & 1;

        // per-lane ldmatrix base addresses (ddy=0), bytes
        uint32_t abase[MT_W];
        #pragma unroll
        for (int mi = 0; mi < MT_W; ++mi) {
            int m0 = (mg + mi * MGROUPS) * 16;
            int qq = m0 + mrow;
            int bl = qq / Q;
            int q2 = qq % Q;
            int jy = q2 / JW, jx = q2 % JW;
            abase[mi] = s_in_b
                + (uint32_t)((bl * CH + (jy + py) * SR + jx + lddx + px) * SIT)
                  * 2;
        }

        float acc[MT_W][NT_W][4];
        #pragma unroll
        for (int mi = 0; mi < MT_W; ++mi)
            #pragma unroll
            for (int ni = 0; ni < NT_W; ++ni)
                #pragma unroll
                for (int k = 0; k < 4; ++k) acc[mi][ni][k] = 0.0f;

        for (int kc = 0; kc < NKCH; ++kc) {
            const int t = p * NKCH + kc;
            asm volatile("cp.async.wait_group 0;");
            __syncthreads();           // chunk t visible; chunk t-1 reads done
            if (t + 1 < NCH) issue_chunk(t + 1);

            const uint32_t* wb = s_wb[t & 1];
            #pragma unroll
            for (int s = 0; s < SPC; ++s) {
                const int ss = kc * SPC + s;     // global s-step in parity
                const uint32_t aoff = (uint32_t)((ss & 1) * SR * SIT * 2
                                                 + (ss >> 1) * 16);
                uint32_t a[MT_W][4];
                #pragma unroll
                for (int mi = 0; mi < MT_W; ++mi)
                    ldsm_x4(a[mi], abase[mi] + aoff);
                const uint32_t* sb = wb + (s * 8 + q) * WBS2 + ln4;
                #pragma unroll
                for (int ni = 0; ni < NT_W; ++ni) {
                    int n0 = (ng * NT_W + ni) * 8;
                    uint32_t bb0 = sb[n0];
                    uint32_t bb1 = sb[n0 + 4 * WBS2];
                    #pragma unroll
                    for (int mi = 0; mi < MT_W; ++mi)
                        mma_f16(acc[mi][ni], a[mi], bb0, bb1);
                }
            }
        }

        // ---- epilogue (overlaps next parity's weight cp.async) ----
        #pragma unroll
        for (int mi = 0; mi < MT_W; ++mi) {
            int m0 = (mg + mi * MGROUPS) * 16;
            int bl = m0 / Q;
            int q0 = m0 % Q;
            #pragma unroll
            for (int ni = 0; ni < NT_W; ++ni) {
                int oc = (ng * NT_W + ni) * 8 + 2 * q;
                if (ONHWC) {
                    float bv0 = bias[oc], bv1 = bias[oc + 1];
                    #pragma unroll
                    for (int h = 0; h < 2; ++h) {
                        int qq = q0 + ln4 + h * 8;
                        int jy = qq / JW, jx = qq % JW;
                        int oy = 2 * (jy0 + jy) + py, ox = 2 * jx + px;
                        float v0 = acc[mi][ni][2 * h + 0] + bv0;
                        float v1 = acc[mi][ni][2 * h + 1] + bv1;
                        if (RELU) { v0 = fmaxf(v0, 0.0f); v1 = fmaxf(v1, 0.0f); }
                        size_t o = ((size_t)(b0 + bl) * OH * OW
                                    + (size_t)oy * OW + ox) * OC + oc;
                        *reinterpret_cast<__half2*>(
                            reinterpret_cast<__half*>(out) + o) =
                            __floats2half2_rn(v0, v1);
                    }
                } else {
                    bool v0ok = (OCV == OC) || (oc < OCV);
                    bool v1ok = (OCV == OC) || (oc + 1 < OCV);
                    float bv0 = v0ok ? bias[oc] : 0.0f;
                    float bv1 = v1ok ? bias[oc + 1] : 0.0f;
                    #pragma unroll
                    for (int h = 0; h < 2; ++h) {
                        int qq = q0 + ln4 + h * 8;
                        int jy = qq / JW, jx = qq % JW;
                        int oy = 2 * (jy0 + jy) + py, ox = 2 * jx + px;
                        size_t o = (((size_t)(b0 + bl) * OCV + oc) * OH + oy)
                                   * OW + ox;
                        float v0 = acc[mi][ni][2 * h + 0] + bv0;
                        float v1 = acc[mi][ni][2 * h + 1] + bv1;
                        if (RELU) { v0 = fmaxf(v0, 0.0f); v1 = fmaxf(v1, 0.0f); }
                        if (v0ok) stv(out + o, v0);
                        if (v1ok) stv(out + o + (size_t)OH * OW, v1);
                    }
                }
            }
        }
    }
}

// ---------------------------------------------------------------------------
extern "C" void kernel_launch(void* const* d_in, const int* in_sizes, int n_in,
                              void* d_out, int out_size) {
    (void)in_sizes; (void)n_in; (void)out_size;
    const float* x  = (const float*)d_in[0];
    const float* gw = (const float*)d_in[1];
    const float* gb = (const float*)d_in[2];
    const float* z  = (const float*)d_in[3];
    const float* w1 = (const float*)d_in[4];
    const float* b1 = (const float*)d_in[5];
    const float* w2 = (const float*)d_in[6];
    const float* b2 = (const float*)d_in[7];
    const float* w3 = (const float*)d_in[8];
    const float* b3 = (const float*)d_in[9];
    float* out = (float*)d_out;

    __half *px0, *pa1, *pa2;
    uint32_t *pw1t, *pw2t, *pw3t;
    cudaGetSymbolAddress((void**)&px0, g_x0);
    cudaGetSymbolAddress((void**)&pa1, g_a1);
    cudaGetSymbolAddress((void**)&pa2, g_a2);
    cudaGetSymbolAddress((void**)&pw1t, g_w1t);
    cudaGetSymbolAddress((void**)&pw2t, g_w2t);
    cudaGetSymbolAddress((void**)&pw3t, g_w3t);

    // conv1 (R12 shape): NB=2, 8 warps, MG=2/MT=4, NG=4/NT=4; KCH=64
    constexpr int S1 = 2 * 100 * 136 * 2 + 2 * 32 * 136 * 4;  // 89,216
    // conv2 (R12 shape): NB=1, 8 warps, MG=4/MT=4, NG=2/NT=4; KCH=64
    constexpr int S2 = 324 * 136 * 2 + 2 * 32 * 72 * 4;       // 106,560
    // conv3 (R12 shape): JHT=16, 8 warps, MG=8/MT=4, NG=1/NT=1; KCH=64
    constexpr int S3 = 612 * 72 * 2 + 2 * 32 * 8 * 4;         // 90,176

    auto k1 = convt_mma_kernel<8, 8, 8, 128, 128, 128, 2, 2, 4, 4, 4, 8, 136,
                               true, __half, 2, true, 64>;
    auto k2 = convt_mma_kernel<16, 16, 16, 128, 64, 64, 1, 4, 2, 4, 4, 8, 72,
                               true, __half, 2, true, 64>;
    auto k3 = convt_mma_kernel<32, 16, 32, 64, 8, 3, 1, 8, 1, 4, 1, 8, 8,
                               false, float, 2, false, 64>;

    cudaFuncSetAttribute(k1, cudaFuncAttributeMaxDynamicSharedMemorySize, S1);
    cudaFuncSetAttribute(k2, cudaFuncAttributeMaxDynamicSharedMemorySize, S2);
    cudaFuncSetAttribute(k3, cudaFuncAttributeMaxDynamicSharedMemorySize, S3);

    prep_kernel<<<848, 256>>>(x, gw, gb, w1, w2, w3);
    mix_kernel<<<16, 256>>>(z);

    k1<<<dim3(B_ / 2, 1), 256, S1>>>(px0, pw1t, b1, pa1);
    k2<<<dim3(B_, 1), 256, S2>>>(pa1, pw2t, b2, pa2);
    k3<<<dim3(B_, 2), 256, S3>>>(pa2, pw3t, b3, out);
}